// round 11
// baseline (speedup 1.0000x reference)
#include <cuda_runtime.h>
#include <math.h>
#include <stdint.h>

#define BATCH  256
#define D      512
#define S      196
#define NKQ    16            // gemm k-slices (32 e each)
#define NOCT   8             // octs per batch (64 d-rows each)
#define OROWS  64            // rows per oct
#define NTILES (BATCH * NOCT)
#define TILE_F (OROWS * S)   // floats per tile (12544)

// device scratch (no allocs allowed)
__device__ float g_vp[NKQ][BATCH][D];        // k-slice partials of v = u @ W (8 MB)
__device__ float g_rai[BATCH][NOCT][256];    // per-oct partial logits (2 MB)
__device__ unsigned int g_cnt[BATCH];        // per-batch completion counters

__device__ __forceinline__ void cp_async16(uint32_t saddr, const void* gaddr) {
    asm volatile("cp.async.cg.shared.global [%0], [%1], 16;"
                 :: "r"(saddr), "l"(gaddr) : "memory");
}
__device__ __forceinline__ uint32_t smem_u32(const void* p) {
    return (uint32_t)__cvta_generic_to_shared(p);
}

// ---------------------------------------------------------------------------
// GEMM partials: g_vp[kq][b][d] = sum_{e in 32-slice} (ctrl[b,e]*w_attn[e])*W[e,d].
// Grid (32 b-tiles, 16 k-slices), 256 threads; 8b x 4d register tile/thread.
// Also zeroes g_cnt (stream-ordered before the fused kernel).
// ---------------------------------------------------------------------------
__global__ __launch_bounds__(256) void gemm_kernel(
    const float* __restrict__ ctrl,
    const float* __restrict__ W,
    const float* __restrict__ w_attn)
{
    __shared__ __align__(16) float u_s[32 * 8];
    __shared__ __align__(16) float part[8 * 512];

    const int tid = threadIdx.x;
    const int dl  = tid & 127;
    const int eh  = tid >> 7;
    const int b0  = blockIdx.x * 8;
    const int kq  = blockIdx.y;
    const int e0  = kq * 32;
    const int d0  = dl * 4;

    if (blockIdx.x == 0 && blockIdx.y == 0 && tid < BATCH)
        g_cnt[tid] = 0;

    {
        int el = tid & 31, j = tid >> 5;
        u_s[el * 8 + j] = ctrl[(b0 + j) * D + e0 + el] * w_attn[e0 + el];
    }
    __syncthreads();

    float acc[8][4];
#pragma unroll
    for (int j = 0; j < 8; j++)
#pragma unroll
        for (int i = 0; i < 4; i++) acc[j][i] = 0.f;

#pragma unroll 4
    for (int i = 0; i < 16; i++) {
        const int el = eh * 16 + i;
        const float4 w4 = *reinterpret_cast<const float4*>(W + (size_t)(e0 + el) * D + d0);
        const float4 ua = *reinterpret_cast<const float4*>(&u_s[el * 8]);
        const float4 ub = *reinterpret_cast<const float4*>(&u_s[el * 8 + 4]);
        acc[0][0] += ua.x * w4.x; acc[0][1] += ua.x * w4.y; acc[0][2] += ua.x * w4.z; acc[0][3] += ua.x * w4.w;
        acc[1][0] += ua.y * w4.x; acc[1][1] += ua.y * w4.y; acc[1][2] += ua.y * w4.z; acc[1][3] += ua.y * w4.w;
        acc[2][0] += ua.z * w4.x; acc[2][1] += ua.z * w4.y; acc[2][2] += ua.z * w4.z; acc[2][3] += ua.z * w4.w;
        acc[3][0] += ua.w * w4.x; acc[3][1] += ua.w * w4.y; acc[3][2] += ua.w * w4.z; acc[3][3] += ua.w * w4.w;
        acc[4][0] += ub.x * w4.x; acc[4][1] += ub.x * w4.y; acc[4][2] += ub.x * w4.z; acc[4][3] += ub.x * w4.w;
        acc[5][0] += ub.y * w4.x; acc[5][1] += ub.y * w4.y; acc[5][2] += ub.y * w4.z; acc[5][3] += ub.y * w4.w;
        acc[6][0] += ub.z * w4.x; acc[6][1] += ub.z * w4.y; acc[6][2] += ub.z * w4.z; acc[6][3] += ub.z * w4.w;
        acc[7][0] += ub.w * w4.x; acc[7][1] += ub.w * w4.y; acc[7][2] += ub.w * w4.z; acc[7][3] += ub.w * w4.w;
    }

    if (eh == 1) {
#pragma unroll
        for (int j = 0; j < 8; j++)
            *reinterpret_cast<float4*>(&part[j * 512 + d0]) =
                make_float4(acc[j][0], acc[j][1], acc[j][2], acc[j][3]);
    }
    __syncthreads();
    if (eh == 0) {
#pragma unroll
        for (int j = 0; j < 8; j++) {
            float4 p = *reinterpret_cast<const float4*>(&part[j * 512 + d0]);
            *reinterpret_cast<float4*>(&g_vp[kq][b0 + j][d0]) =
                make_float4(acc[j][0] + p.x, acc[j][1] + p.y,
                            acc[j][2] + p.z, acc[j][3] + p.w);
        }
    }
}

// ---------------------------------------------------------------------------
// Persistent fused kernel, 512 threads, grid = 2*SMs (divisible by 8, all
// resident). Double-buffered: prefetch of tile k+1 issued at the TOP of
// iteration k (its buffer was freed last iteration), wait_group 1 releases
// tile k while k+1 streams underneath the entire body. Batch-mates are the
// 8 adjacent CTAs at the same depth -> minimal spin skew, no cross-depth deps.
// ---------------------------------------------------------------------------
__global__ __launch_bounds__(512) void fused_kernel(
    const float* __restrict__ kb,      // [B, D, S]
    const float* __restrict__ memory,
    const float* __restrict__ ctrl,
    const float* __restrict__ w_attn,
    float* __restrict__ out)           // [B, D]
{
    extern __shared__ __align__(16) float buf[];   // 2 * TILE_F floats

    const int tid  = threadIdx.x;
    const int wid  = tid >> 5;
    const int lane = tid & 31;
    const int l2   = lane < 17 ? lane : 16;     // clamped second segment
    const float mB = lane < 17 ? 1.f : 0.f;
    const int nct  = gridDim.x;

    __shared__ float w_s[OROWS];
    __shared__ __align__(16) float part[8][200];
    __shared__ __align__(16) float rvi_s[208];
    __shared__ float red[16];

    // ---- prologue: prefetch first tile into buffer 0 ----
    int t = blockIdx.x;
    if (t < NTILES) {
        const float* gsrc = kb + (size_t)t * TILE_F;
        const uint32_t sb = smem_u32(buf);
        for (int idx = tid; idx < TILE_F / 4; idx += 512)
            cp_async16(sb + idx * 16, gsrc + idx * 4);
    }
    asm volatile("cp.async.commit_group;" ::: "memory");

    for (int k = 0; t < NTILES; k++, t += nct) {
        float* cur = buf + (k & 1) * TILE_F;
        float* nxt = buf + ((k + 1) & 1) * TILE_F;
        const int b   = t >> 3;
        const int oct = t & 7;
        const int tn  = t + nct;

        // ---- prefetch NEXT tile immediately (nxt freed last iteration);
        //      it streams under the whole body of this iteration ----
        if (tn < NTILES) {
            const float* gsrc = kb + (size_t)tn * TILE_F;
            const uint32_t sb = smem_u32(nxt);
            for (int idx = tid; idx < TILE_F / 4; idx += 512)
                cp_async16(sb + idx * 16, gsrc + idx * 4);
        }
        asm volatile("cp.async.commit_group;" ::: "memory");

        // finalize w for this tile's 64 rows (L2 loads, overlap the fills)
        if (tid < OROWS) {
            const int dg = oct * OROWS + tid;
            float v = 0.f;
#pragma unroll
            for (int kk = 0; kk < NKQ; kk++) v += g_vp[kk][b][dg];
            w_s[tid] = memory[b * D + dg] * v + ctrl[b * D + dg] * w_attn[dg];
        }

        // wait for tile k only (<=1 group pending: tile k+1 stays in flight)
        asm volatile("cp.async.wait_group 1;" ::: "memory");
        __syncthreads();

        // ---- Pass 1: partial logits from smem (4 rows per warp) ----
        float4 accA = make_float4(0.f, 0.f, 0.f, 0.f);
        float4 accB = make_float4(0.f, 0.f, 0.f, 0.f);
#pragma unroll
        for (int r = wid; r < OROWS; r += 16) {
            const float wv = w_s[r];
            const float4* row = reinterpret_cast<const float4*>(&cur[r * S]);
            float4 va = row[lane];
            float4 vb = row[32 + l2];
            accA.x += wv * va.x;  accA.y += wv * va.y;
            accA.z += wv * va.z;  accA.w += wv * va.w;
            float wb = wv * mB;
            accB.x += wb * vb.x;  accB.y += wb * vb.y;
            accB.z += wb * vb.z;  accB.w += wb * vb.w;
        }

        // two-round cross-warp reduction (deterministic)
        if (wid >= 8) {
            *reinterpret_cast<float4*>(&part[wid - 8][4 * lane]) = accA;
            if (lane < 17)
                *reinterpret_cast<float4*>(&part[wid - 8][128 + 4 * lane]) = accB;
        }
        __syncthreads();
        if (wid < 8) {
            float4 pA = *reinterpret_cast<const float4*>(&part[wid][4 * lane]);
            accA.x += pA.x; accA.y += pA.y; accA.z += pA.z; accA.w += pA.w;
            *reinterpret_cast<float4*>(&part[wid][4 * lane]) = accA;
            if (lane < 17) {
                float4 pB = *reinterpret_cast<const float4*>(&part[wid][128 + 4 * lane]);
                accB.x += pB.x; accB.y += pB.y; accB.z += pB.z; accB.w += pB.w;
                *reinterpret_cast<float4*>(&part[wid][128 + 4 * lane]) = accB;
            }
        }
        __syncthreads();

        if (tid < S) {
            float sum = 0.f;
#pragma unroll
            for (int w = 0; w < 8; w++) sum += part[w][tid];
            g_rai[b][oct][tid] = sum;
        }
        __syncthreads();

        // signal my oct done, then single-thread spin for the other 7
        if (tid == 0) {
            __threadfence();
            atomicAdd(&g_cnt[b], 1u);
            unsigned v;
            do {
                asm volatile("ld.acquire.gpu.global.u32 %0, [%1];"
                             : "=r"(v) : "l"(&g_cnt[b]) : "memory");
                if (v < (unsigned)NOCT) __nanosleep(128);
            } while (v < (unsigned)NOCT);
        }
        __syncthreads();   // chains tid0's acquire to the whole block

        // full rai = fixed-order sum of 8 oct-partials (deterministic)
        float rai = -INFINITY;
        if (tid < S) {
            float sum = 0.f;
#pragma unroll
            for (int kk = 0; kk < NOCT; kk++) sum += g_rai[b][kk][tid];
            rai = sum;
        }

        // ---- softmax over s ----
        float m = rai;
#pragma unroll
        for (int off = 16; off > 0; off >>= 1)
            m = fmaxf(m, __shfl_xor_sync(0xffffffff, m, off));
        if (lane == 0) red[wid] = m;
        __syncthreads();
        if (wid == 0) {
            float v = (lane < 16) ? red[lane] : -INFINITY;
#pragma unroll
            for (int off = 8; off > 0; off >>= 1)
                v = fmaxf(v, __shfl_xor_sync(0xffffffff, v, off));
            if (lane == 0) red[0] = v;
        }
        __syncthreads();
        const float gmax = red[0];
        __syncthreads();

        float p = (tid < S) ? expf(rai - gmax) : 0.f;
        float sacc = p;
#pragma unroll
        for (int off = 16; off > 0; off >>= 1)
            sacc += __shfl_xor_sync(0xffffffff, sacc, off);
        if (lane == 0) red[wid] = sacc;
        __syncthreads();
        if (wid == 0) {
            float v = (lane < 16) ? red[lane] : 0.f;
#pragma unroll
            for (int off = 8; off > 0; off >>= 1)
                v += __shfl_xor_sync(0xffffffff, v, off);
            if (lane == 0) red[0] = v;
        }
        __syncthreads();
        const float inv_sum = 1.f / red[0];
        if (tid < S) rvi_s[tid] = p * inv_sum;
        if (tid >= S && tid < 208) rvi_s[tid] = 0.f;
        __syncthreads();

        const float4 rA = *reinterpret_cast<const float4*>(&rvi_s[4 * lane]);
        const float4 rB = *reinterpret_cast<const float4*>(&rvi_s[128 + 4 * l2]);

        // ---- Pass 2: weighted sum from smem (4 rows per warp) ----
#pragma unroll
        for (int r = wid; r < OROWS; r += 16) {
            const float4* row = reinterpret_cast<const float4*>(&cur[r * S]);
            float4 va = row[lane];
            float4 vb = row[32 + l2];
            float sum = va.x * rA.x + va.y * rA.y + va.z * rA.z + va.w * rA.w
                      + mB * (vb.x * rB.x + vb.y * rB.y + vb.z * rB.z + vb.w * rB.w);
#pragma unroll
            for (int off = 16; off > 0; off >>= 1)
                sum += __shfl_xor_sync(0xffffffff, sum, off);
            if (lane == 0) out[b * D + oct * OROWS + r] = sum;
        }
        __syncthreads();   // cur buffer free for the prefetch next iteration
    }
}

extern "C" void kernel_launch(void* const* d_in, const int* in_sizes, int n_in,
                              void* d_out, int out_size)
{
    const float* memory = (const float*)d_in[0];  // [B, D]
    const float* ctrl   = (const float*)d_in[1];  // [B, D]
    const float* kb     = (const float*)d_in[2];  // [B, D, S]
    const float* W      = (const float*)d_in[3];  // [D, D]
    // d_in[4] = b_concat: s-independent shift inside softmax -> drops out
    const float* w_attn = (const float*)d_in[5];  // [D]
    float* out = (float*)d_out;                   // [B, D]

    int dev = 0, nsm = 148;
    cudaGetDevice(&dev);
    cudaDeviceGetAttribute(&nsm, cudaDevAttrMultiProcessorCount, dev);

    const int dyn_smem = 2 * TILE_F * sizeof(float);   // 100352 B
    cudaFuncSetAttribute(fused_kernel,
                         cudaFuncAttributeMaxDynamicSharedMemorySize, dyn_smem);

    gemm_kernel<<<dim3(32, NKQ), 256>>>(ctrl, W, w_attn);
    fused_kernel<<<2 * nsm, 512, dyn_smem>>>(kb, memory, ctrl, w_attn, out);
}

// round 12
// speedup vs baseline: 1.0042x; 1.0042x over previous
#include <cuda_runtime.h>
#include <math.h>
#include <stdint.h>

#define BATCH  256
#define D      512
#define S      196
#define NKQ    16            // gemm k-slices (32 e each)
#define NOCT   8             // octs per batch (64 d-rows each)
#define OROWS  64            // rows per oct
#define NTILES (BATCH * NOCT)
#define TILE_F (OROWS * S)   // floats per tile (12544)
#define TILE_B (TILE_F * 4)  // bytes per tile  (50176)

// device scratch (no allocs allowed)
__device__ float g_vp[NKQ][BATCH][D];        // k-slice partials of v = u @ W (8 MB)
__device__ float g_rai[BATCH][NOCT][256];    // per-oct partial logits (2 MB)
__device__ unsigned int g_cnt[BATCH];        // per-batch completion counters

__device__ __forceinline__ uint32_t smem_u32(const void* p) {
    return (uint32_t)__cvta_generic_to_shared(p);
}
__device__ __forceinline__ void mbar_init(uint32_t mbar, uint32_t count) {
    asm volatile("mbarrier.init.shared.b64 [%0], %1;" :: "r"(mbar), "r"(count) : "memory");
}
__device__ __forceinline__ void mbar_expect_tx(uint32_t mbar, uint32_t bytes) {
    asm volatile("mbarrier.arrive.expect_tx.shared.b64 _, [%0], %1;"
                 :: "r"(mbar), "r"(bytes) : "memory");
}
// one-instruction bulk copy: global -> shared, completion -> mbarrier tx bytes
__device__ __forceinline__ void bulk_g2s(uint32_t dst, const void* src,
                                         uint32_t bytes, uint32_t mbar) {
    asm volatile(
        "cp.async.bulk.shared::cluster.global.mbarrier::complete_tx::bytes "
        "[%0], [%1], %2, [%3];"
        :: "r"(dst), "l"(src), "r"(bytes), "r"(mbar) : "memory");
}
__device__ __forceinline__ void mbar_wait(uint32_t mbar, uint32_t parity) {
    uint32_t done;
    asm volatile(
        "{\n\t.reg .pred p;\n\t"
        "mbarrier.try_wait.parity.acquire.cta.shared::cta.b64 p, [%1], %2;\n\t"
        "selp.b32 %0, 1, 0, p;\n\t}"
        : "=r"(done) : "r"(mbar), "r"(parity) : "memory");
    while (!done) {
        asm volatile(
            "{\n\t.reg .pred p;\n\t"
            "mbarrier.try_wait.parity.acquire.cta.shared::cta.b64 p, [%1], %2, 0x989680;\n\t"
            "selp.b32 %0, 1, 0, p;\n\t}"
            : "=r"(done) : "r"(mbar), "r"(parity) : "memory");
    }
}

// ---------------------------------------------------------------------------
// GEMM partials: g_vp[kq][b][d] = sum_{e in 32-slice} (ctrl[b,e]*w_attn[e])*W[e,d].
// Grid (32 b-tiles, 16 k-slices), 256 threads; 8b x 4d register tile/thread.
// Also zeroes g_cnt (stream-ordered before the fused kernel).
// ---------------------------------------------------------------------------
__global__ __launch_bounds__(256) void gemm_kernel(
    const float* __restrict__ ctrl,
    const float* __restrict__ W,
    const float* __restrict__ w_attn)
{
    __shared__ __align__(16) float u_s[32 * 8];
    __shared__ __align__(16) float part[8 * 512];

    const int tid = threadIdx.x;
    const int dl  = tid & 127;
    const int eh  = tid >> 7;
    const int b0  = blockIdx.x * 8;
    const int kq  = blockIdx.y;
    const int e0  = kq * 32;
    const int d0  = dl * 4;

    if (blockIdx.x == 0 && blockIdx.y == 0 && tid < BATCH)
        g_cnt[tid] = 0;

    {
        int el = tid & 31, j = tid >> 5;
        u_s[el * 8 + j] = ctrl[(b0 + j) * D + e0 + el] * w_attn[e0 + el];
    }
    __syncthreads();

    float acc[8][4];
#pragma unroll
    for (int j = 0; j < 8; j++)
#pragma unroll
        for (int i = 0; i < 4; i++) acc[j][i] = 0.f;

#pragma unroll 4
    for (int i = 0; i < 16; i++) {
        const int el = eh * 16 + i;
        const float4 w4 = *reinterpret_cast<const float4*>(W + (size_t)(e0 + el) * D + d0);
        const float4 ua = *reinterpret_cast<const float4*>(&u_s[el * 8]);
        const float4 ub = *reinterpret_cast<const float4*>(&u_s[el * 8 + 4]);
        acc[0][0] += ua.x * w4.x; acc[0][1] += ua.x * w4.y; acc[0][2] += ua.x * w4.z; acc[0][3] += ua.x * w4.w;
        acc[1][0] += ua.y * w4.x; acc[1][1] += ua.y * w4.y; acc[1][2] += ua.y * w4.z; acc[1][3] += ua.y * w4.w;
        acc[2][0] += ua.z * w4.x; acc[2][1] += ua.z * w4.y; acc[2][2] += ua.z * w4.z; acc[2][3] += ua.z * w4.w;
        acc[3][0] += ua.w * w4.x; acc[3][1] += ua.w * w4.y; acc[3][2] += ua.w * w4.z; acc[3][3] += ua.w * w4.w;
        acc[4][0] += ub.x * w4.x; acc[4][1] += ub.x * w4.y; acc[4][2] += ub.x * w4.z; acc[4][3] += ub.x * w4.w;
        acc[5][0] += ub.y * w4.x; acc[5][1] += ub.y * w4.y; acc[5][2] += ub.y * w4.z; acc[5][3] += ub.y * w4.w;
        acc[6][0] += ub.z * w4.x; acc[6][1] += ub.z * w4.y; acc[6][2] += ub.z * w4.z; acc[6][3] += ub.z * w4.w;
        acc[7][0] += ub.w * w4.x; acc[7][1] += ub.w * w4.y; acc[7][2] += ub.w * w4.z; acc[7][3] += ub.w * w4.w;
    }

    if (eh == 1) {
#pragma unroll
        for (int j = 0; j < 8; j++)
            *reinterpret_cast<float4*>(&part[j * 512 + d0]) =
                make_float4(acc[j][0], acc[j][1], acc[j][2], acc[j][3]);
    }
    __syncthreads();
    if (eh == 0) {
#pragma unroll
        for (int j = 0; j < 8; j++) {
            float4 p = *reinterpret_cast<const float4*>(&part[j * 512 + d0]);
            *reinterpret_cast<float4*>(&g_vp[kq][b0 + j][d0]) =
                make_float4(acc[j][0] + p.x, acc[j][1] + p.y,
                            acc[j][2] + p.z, acc[j][3] + p.w);
        }
    }
}

// ---------------------------------------------------------------------------
// Persistent fused kernel, 512 threads, grid = 2*SMs (divisible by 8, all
// resident). Double-buffered with ONE cp.async.bulk per tile (mbarrier
// completion): prefetch of tile k+1 issued at the top of iteration k and
// streams under the whole body. Batch-mates are 8 adjacent CTAs at the same
// depth. kb read from DRAM exactly once; both passes run from smem.
// ---------------------------------------------------------------------------
__global__ __launch_bounds__(512) void fused_kernel(
    const float* __restrict__ kb,      // [B, D, S]
    const float* __restrict__ memory,
    const float* __restrict__ ctrl,
    const float* __restrict__ w_attn,
    float* __restrict__ out)           // [B, D]
{
    extern __shared__ __align__(16) float buf[];   // 2 * TILE_F floats

    const int tid  = threadIdx.x;
    const int wid  = tid >> 5;
    const int lane = tid & 31;
    const int l2   = lane < 17 ? lane : 16;     // clamped second segment
    const float mB = lane < 17 ? 1.f : 0.f;
    const int nct  = gridDim.x;

    __shared__ float w_s[OROWS];
    __shared__ __align__(16) float part[8][200];
    __shared__ __align__(16) float rvi_s[208];
    __shared__ float red[16];
    __shared__ __align__(8) unsigned long long mbar_store[2];

    const uint32_t mbar0 = smem_u32(&mbar_store[0]);
    const uint32_t mbar1 = smem_u32(&mbar_store[1]);

    if (tid == 0) {
        mbar_init(mbar0, 1);
        mbar_init(mbar1, 1);
    }
    __syncthreads();

    int ph0 = 0, ph1 = 0;

    // ---- prologue: prefetch first tile into buffer 0 ----
    int t = blockIdx.x;
    if (t < NTILES && tid == 0) {
        mbar_expect_tx(mbar0, TILE_B);
        bulk_g2s(smem_u32(buf), kb + (size_t)t * TILE_F, TILE_B, mbar0);
    }

    for (int k = 0; t < NTILES; k++, t += nct) {
        float* cur = buf + (k & 1) * TILE_F;
        float* nxt = buf + ((k + 1) & 1) * TILE_F;
        const uint32_t mcur = (k & 1) ? mbar1 : mbar0;
        const uint32_t mnxt = (k & 1) ? mbar0 : mbar1;
        const int b   = t >> 3;
        const int oct = t & 7;
        const int tn  = t + nct;

        // ---- prefetch NEXT tile (its buffer was freed last iteration) ----
        if (tn < NTILES && tid == 0) {
            mbar_expect_tx(mnxt, TILE_B);
            bulk_g2s(smem_u32(nxt), kb + (size_t)tn * TILE_F, TILE_B, mnxt);
        }

        // finalize w for this tile's 64 rows (L2 loads overlap the fills)
        if (tid < OROWS) {
            const int dg = oct * OROWS + tid;
            float v = 0.f;
#pragma unroll
            for (int kk = 0; kk < NKQ; kk++) v += g_vp[kk][b][dg];
            w_s[tid] = memory[b * D + dg] * v + ctrl[b * D + dg] * w_attn[dg];
        }

        // ---- wait for current tile's bulk copy ----
        if (k & 1) { mbar_wait(mcur, ph1); ph1 ^= 1; }
        else       { mbar_wait(mcur, ph0); ph0 ^= 1; }
        __syncthreads();

        // ---- Pass 1: partial logits from smem (4 rows per warp) ----
        float4 accA = make_float4(0.f, 0.f, 0.f, 0.f);
        float4 accB = make_float4(0.f, 0.f, 0.f, 0.f);
#pragma unroll
        for (int r = wid; r < OROWS; r += 16) {
            const float wv = w_s[r];
            const float4* row = reinterpret_cast<const float4*>(&cur[r * S]);
            float4 va = row[lane];
            float4 vb = row[32 + l2];
            accA.x += wv * va.x;  accA.y += wv * va.y;
            accA.z += wv * va.z;  accA.w += wv * va.w;
            float wb = wv * mB;
            accB.x += wb * vb.x;  accB.y += wb * vb.y;
            accB.z += wb * vb.z;  accB.w += wb * vb.w;
        }

        // two-round cross-warp reduction (deterministic)
        if (wid >= 8) {
            *reinterpret_cast<float4*>(&part[wid - 8][4 * lane]) = accA;
            if (lane < 17)
                *reinterpret_cast<float4*>(&part[wid - 8][128 + 4 * lane]) = accB;
        }
        __syncthreads();
        if (wid < 8) {
            float4 pA = *reinterpret_cast<const float4*>(&part[wid][4 * lane]);
            accA.x += pA.x; accA.y += pA.y; accA.z += pA.z; accA.w += pA.w;
            *reinterpret_cast<float4*>(&part[wid][4 * lane]) = accA;
            if (lane < 17) {
                float4 pB = *reinterpret_cast<const float4*>(&part[wid][128 + 4 * lane]);
                accB.x += pB.x; accB.y += pB.y; accB.z += pB.z; accB.w += pB.w;
                *reinterpret_cast<float4*>(&part[wid][128 + 4 * lane]) = accB;
            }
        }
        __syncthreads();

        if (tid < S) {
            float sum = 0.f;
#pragma unroll
            for (int w = 0; w < 8; w++) sum += part[w][tid];
            g_rai[b][oct][tid] = sum;
        }
        __syncthreads();

        // signal my oct done, then single-thread spin for the other 7
        if (tid == 0) {
            __threadfence();
            atomicAdd(&g_cnt[b], 1u);
            unsigned v;
            do {
                asm volatile("ld.acquire.gpu.global.u32 %0, [%1];"
                             : "=r"(v) : "l"(&g_cnt[b]) : "memory");
                if (v < (unsigned)NOCT) __nanosleep(128);
            } while (v < (unsigned)NOCT);
        }
        __syncthreads();   // chains tid0's acquire to the whole block

        // full rai = fixed-order sum of 8 oct-partials (deterministic)
        float rai = -INFINITY;
        if (tid < S) {
            float sum = 0.f;
#pragma unroll
            for (int kk = 0; kk < NOCT; kk++) sum += g_rai[b][kk][tid];
            rai = sum;
        }

        // ---- softmax over s ----
        float m = rai;
#pragma unroll
        for (int off = 16; off > 0; off >>= 1)
            m = fmaxf(m, __shfl_xor_sync(0xffffffff, m, off));
        if (lane == 0) red[wid] = m;
        __syncthreads();
        if (wid == 0) {
            float v = (lane < 16) ? red[lane] : -INFINITY;
#pragma unroll
            for (int off = 8; off > 0; off >>= 1)
                v = fmaxf(v, __shfl_xor_sync(0xffffffff, v, off));
            if (lane == 0) red[0] = v;
        }
        __syncthreads();
        const float gmax = red[0];
        __syncthreads();

        float p = (tid < S) ? expf(rai - gmax) : 0.f;
        float sacc = p;
#pragma unroll
        for (int off = 16; off > 0; off >>= 1)
            sacc += __shfl_xor_sync(0xffffffff, sacc, off);
        if (lane == 0) red[wid] = sacc;
        __syncthreads();
        if (wid == 0) {
            float v = (lane < 16) ? red[lane] : 0.f;
#pragma unroll
            for (int off = 8; off > 0; off >>= 1)
                v += __shfl_xor_sync(0xffffffff, v, off);
            if (lane == 0) red[0] = v;
        }
        __syncthreads();
        const float inv_sum = 1.f / red[0];
        if (tid < S) rvi_s[tid] = p * inv_sum;
        if (tid >= S && tid < 208) rvi_s[tid] = 0.f;
        __syncthreads();

        const float4 rA = *reinterpret_cast<const float4*>(&rvi_s[4 * lane]);
        const float4 rB = *reinterpret_cast<const float4*>(&rvi_s[128 + 4 * l2]);

        // ---- Pass 2: weighted sum from smem (4 rows per warp) ----
#pragma unroll
        for (int r = wid; r < OROWS; r += 16) {
            const float4* row = reinterpret_cast<const float4*>(&cur[r * S]);
            float4 va = row[lane];
            float4 vb = row[32 + l2];
            float sum = va.x * rA.x + va.y * rA.y + va.z * rA.z + va.w * rA.w
                      + mB * (vb.x * rB.x + vb.y * rB.y + vb.z * rB.z + vb.w * rB.w);
#pragma unroll
            for (int off = 16; off > 0; off >>= 1)
                sum += __shfl_xor_sync(0xffffffff, sum, off);
            if (lane == 0) out[b * D + oct * OROWS + r] = sum;
        }
        __syncthreads();   // cur buffer free for the prefetch next iteration
    }
}

extern "C" void kernel_launch(void* const* d_in, const int* in_sizes, int n_in,
                              void* d_out, int out_size)
{
    const float* memory = (const float*)d_in[0];  // [B, D]
    const float* ctrl   = (const float*)d_in[1];  // [B, D]
    const float* kb     = (const float*)d_in[2];  // [B, D, S]
    const float* W      = (const float*)d_in[3];  // [D, D]
    // d_in[4] = b_concat: s-independent shift inside softmax -> drops out
    const float* w_attn = (const float*)d_in[5];  // [D]
    float* out = (float*)d_out;                   // [B, D]

    int dev = 0, nsm = 148;
    cudaGetDevice(&dev);
    cudaDeviceGetAttribute(&nsm, cudaDevAttrMultiProcessorCount, dev);

    const int dyn_smem = 2 * TILE_F * sizeof(float);   // 100352 B
    cudaFuncSetAttribute(fused_kernel,
                         cudaFuncAttributeMaxDynamicSharedMemorySize, dyn_smem);

    gemm_kernel<<<dim3(32, NKQ), 256>>>(ctrl, W, w_attn);
    fused_kernel<<<2 * nsm, 512, dyn_smem>>>(kb, memory, ctrl, w_attn, out);
}

// round 13
// speedup vs baseline: 1.2404x; 1.2353x over previous
#include <cuda_runtime.h>
#include <math.h>
#include <stdint.h>

#define BATCH  256
#define D      512
#define S      196
#define NKQ    16           // gemm k-slices (32 e each)
#define NOCT   8            // octs per batch (64 d-rows each)
#define OROWS  64           // rows per oct
#define TILE_F (OROWS * S)  // floats per tile (12544)
#define TILE_B (TILE_F * 4) // bytes per tile  (50176)

// device scratch (no allocs allowed)
__device__ float g_vp[NKQ][BATCH][D];        // k-slice partials of v = u @ W (8 MB)
__device__ float g_rai[BATCH][NOCT][256];    // per-oct partial logits (2 MB)
__device__ unsigned int g_cnt[BATCH];        // per-batch completion counters

__device__ __forceinline__ uint32_t smem_u32(const void* p) {
    return (uint32_t)__cvta_generic_to_shared(p);
}
__device__ __forceinline__ void mbar_init(uint32_t mbar, uint32_t count) {
    asm volatile("mbarrier.init.shared.b64 [%0], %1;" :: "r"(mbar), "r"(count) : "memory");
}
__device__ __forceinline__ void mbar_expect_tx(uint32_t mbar, uint32_t bytes) {
    asm volatile("mbarrier.arrive.expect_tx.shared.b64 _, [%0], %1;"
                 :: "r"(mbar), "r"(bytes) : "memory");
}
// one-instruction bulk copy: global -> shared, completion -> mbarrier tx bytes
__device__ __forceinline__ void bulk_g2s(uint32_t dst, const void* src,
                                         uint32_t bytes, uint32_t mbar) {
    asm volatile(
        "cp.async.bulk.shared::cluster.global.mbarrier::complete_tx::bytes "
        "[%0], [%1], %2, [%3];"
        :: "r"(dst), "l"(src), "r"(bytes), "r"(mbar) : "memory");
}
__device__ __forceinline__ void mbar_wait0(uint32_t mbar) {
    uint32_t done;
    do {
        asm volatile(
            "{\n\t.reg .pred p;\n\t"
            "mbarrier.try_wait.parity.acquire.cta.shared::cta.b64 p, [%1], 0, 0x989680;\n\t"
            "selp.b32 %0, 1, 0, p;\n\t}"
            : "=r"(done) : "r"(mbar) : "memory");
    } while (!done);
}

// ---------------------------------------------------------------------------
// GEMM partials: g_vp[kq][b][d] = sum_{e in 32-slice} (ctrl[b,e]*w_attn[e])*W[e,d].
// Grid (32 b-tiles, 16 k-slices), 256 threads; 8b x 4d register tile/thread.
// Also zeroes g_cnt (stream-ordered before the fused kernel).
// ---------------------------------------------------------------------------
__global__ __launch_bounds__(256) void gemm_kernel(
    const float* __restrict__ ctrl,
    const float* __restrict__ W,
    const float* __restrict__ w_attn)
{
    __shared__ __align__(16) float u_s[32 * 8];
    __shared__ __align__(16) float part[8 * 512];

    const int tid = threadIdx.x;
    const int dl  = tid & 127;
    const int eh  = tid >> 7;
    const int b0  = blockIdx.x * 8;
    const int kq  = blockIdx.y;
    const int e0  = kq * 32;
    const int d0  = dl * 4;

    if (blockIdx.x == 0 && blockIdx.y == 0 && tid < BATCH)
        g_cnt[tid] = 0;

    {
        int el = tid & 31, j = tid >> 5;
        u_s[el * 8 + j] = ctrl[(b0 + j) * D + e0 + el] * w_attn[e0 + el];
    }
    __syncthreads();

    float acc[8][4];
#pragma unroll
    for (int j = 0; j < 8; j++)
#pragma unroll
        for (int i = 0; i < 4; i++) acc[j][i] = 0.f;

#pragma unroll 4
    for (int i = 0; i < 16; i++) {
        const int el = eh * 16 + i;
        const float4 w4 = *reinterpret_cast<const float4*>(W + (size_t)(e0 + el) * D + d0);
        const float4 ua = *reinterpret_cast<const float4*>(&u_s[el * 8]);
        const float4 ub = *reinterpret_cast<const float4*>(&u_s[el * 8 + 4]);
        acc[0][0] += ua.x * w4.x; acc[0][1] += ua.x * w4.y; acc[0][2] += ua.x * w4.z; acc[0][3] += ua.x * w4.w;
        acc[1][0] += ua.y * w4.x; acc[1][1] += ua.y * w4.y; acc[1][2] += ua.y * w4.z; acc[1][3] += ua.y * w4.w;
        acc[2][0] += ua.z * w4.x; acc[2][1] += ua.z * w4.y; acc[2][2] += ua.z * w4.z; acc[2][3] += ua.z * w4.w;
        acc[3][0] += ua.w * w4.x; acc[3][1] += ua.w * w4.y; acc[3][2] += ua.w * w4.z; acc[3][3] += ua.w * w4.w;
        acc[4][0] += ub.x * w4.x; acc[4][1] += ub.x * w4.y; acc[4][2] += ub.x * w4.z; acc[4][3] += ub.x * w4.w;
        acc[5][0] += ub.y * w4.x; acc[5][1] += ub.y * w4.y; acc[5][2] += ub.y * w4.z; acc[5][3] += ub.y * w4.w;
        acc[6][0] += ub.z * w4.x; acc[6][1] += ub.z * w4.y; acc[6][2] += ub.z * w4.z; acc[6][3] += ub.z * w4.w;
        acc[7][0] += ub.w * w4.x; acc[7][1] += ub.w * w4.y; acc[7][2] += ub.w * w4.z; acc[7][3] += ub.w * w4.w;
    }

    if (eh == 1) {
#pragma unroll
        for (int j = 0; j < 8; j++)
            *reinterpret_cast<float4*>(&part[j * 512 + d0]) =
                make_float4(acc[j][0], acc[j][1], acc[j][2], acc[j][3]);
    }
    __syncthreads();
    if (eh == 0) {
#pragma unroll
        for (int j = 0; j < 8; j++) {
            float4 p = *reinterpret_cast<const float4*>(&part[j * 512 + d0]);
            *reinterpret_cast<float4*>(&g_vp[kq][b0 + j][d0]) =
                make_float4(acc[j][0] + p.x, acc[j][1] + p.y,
                            acc[j][2] + p.z, acc[j][3] + p.w);
        }
    }
}

// ---------------------------------------------------------------------------
// Fused kernel (R9 structure + bulk fill). Grid 2048 = (b, oct): each CTA
// stages its 64-row (50 KB contiguous) kb tile with ONE cp.async.bulk,
// finalizes w while the copy flies, computes partial logits from smem,
// signals (release), single-thread spins for the other 7 octs, softmaxes,
// and does the weighted sum from smem. kb read from DRAM exactly once.
// ---------------------------------------------------------------------------
__global__ __launch_bounds__(256) void fused_kernel(
    const float* __restrict__ kb,      // [B, D, S]
    const float* __restrict__ memory,
    const float* __restrict__ ctrl,
    const float* __restrict__ w_attn,
    float* __restrict__ out)           // [B, D]
{
    extern __shared__ __align__(16) float kb_s[];   // TILE_F floats (50176 B)

    const int oct  = blockIdx.x & 7;
    const int b    = blockIdx.x >> 3;
    const int tid  = threadIdx.x;
    const int wid  = tid >> 5;
    const int lane = tid & 31;
    const int l2   = lane < 17 ? lane : 16;     // clamped second segment
    const float mB = lane < 17 ? 1.f : 0.f;

    __shared__ float w_s[OROWS];
    __shared__ __align__(16) float part[4][200];
    __shared__ __align__(16) float rvi_s[208];
    __shared__ float red[8];
    __shared__ __align__(8) unsigned long long mbar_store;

    const uint32_t mbar = smem_u32(&mbar_store);

    if (tid == 0) mbar_init(mbar, 1);
    __syncthreads();

    // ---- stage tile: ONE bulk copy (issue cost ~2 instructions) ----
    if (tid == 0) {
        mbar_expect_tx(mbar, TILE_B);
        bulk_g2s(smem_u32(kb_s),
                 kb + (size_t)b * (D * S) + (size_t)oct * TILE_F,
                 TILE_B, mbar);
    }

    // ---- finalize w for my 64 rows while the copy flies ----
    if (tid < OROWS) {
        const int dg = oct * OROWS + tid;
        float v = 0.f;
#pragma unroll
        for (int k = 0; k < NKQ; k++) v += g_vp[k][b][dg];
        w_s[tid] = memory[b * D + dg] * v + ctrl[b * D + dg] * w_attn[dg];
    }

    mbar_wait0(mbar);
    __syncthreads();

    // ---- Pass 1: partial logits from smem (8 rows per warp) ----
    float4 accA = make_float4(0.f, 0.f, 0.f, 0.f);
    float4 accB = make_float4(0.f, 0.f, 0.f, 0.f);

#pragma unroll
    for (int r = wid; r < OROWS; r += 8) {
        const float wv = w_s[r];
        const float4* __restrict__ row = reinterpret_cast<const float4*>(&kb_s[r * S]);
        float4 va = row[lane];          // s = 4*lane..+3
        float4 vb = row[32 + l2];       // s = 128+4*l2..+3
        accA.x += wv * va.x;  accA.y += wv * va.y;
        accA.z += wv * va.z;  accA.w += wv * va.w;
        float wb = wv * mB;
        accB.x += wb * vb.x;  accB.y += wb * vb.y;
        accB.z += wb * vb.z;  accB.w += wb * vb.w;
    }

    // two-round cross-warp reduction (deterministic): 4..7 store, 0..3 add
    if (wid >= 4) {
        *reinterpret_cast<float4*>(&part[wid - 4][4 * lane]) = accA;
        if (lane < 17)
            *reinterpret_cast<float4*>(&part[wid - 4][128 + 4 * lane]) = accB;
    }
    __syncthreads();
    if (wid < 4) {
        float4 pA = *reinterpret_cast<const float4*>(&part[wid][4 * lane]);
        accA.x += pA.x; accA.y += pA.y; accA.z += pA.z; accA.w += pA.w;
        *reinterpret_cast<float4*>(&part[wid][4 * lane]) = accA;
        if (lane < 17) {
            float4 pB = *reinterpret_cast<const float4*>(&part[wid][128 + 4 * lane]);
            accB.x += pB.x; accB.y += pB.y; accB.z += pB.z; accB.w += pB.w;
            *reinterpret_cast<float4*>(&part[wid][128 + 4 * lane]) = accB;
        }
    }
    __syncthreads();

    if (tid < S)
        g_rai[b][oct][tid] = part[0][tid] + part[1][tid] + part[2][tid] + part[3][tid];
    __syncthreads();

    // ---- signal (release) + single-thread spin: all 8 octs done? ----
    if (tid == 0) {
        unsigned old;
        asm volatile("atom.release.gpu.global.add.u32 %0, [%1], 1;"
                     : "=r"(old) : "l"(&g_cnt[b]) : "memory");
        unsigned v;
        do {
            asm volatile("ld.acquire.gpu.global.u32 %0, [%1];"
                         : "=r"(v) : "l"(&g_cnt[b]) : "memory");
            if (v < (unsigned)NOCT) __nanosleep(128);
        } while (v < (unsigned)NOCT);
    }
    __syncthreads();   // chains tid0's acquire to the whole block

    // full rai = fixed-order sum of 8 oct-partials (deterministic)
    float rai = -INFINITY;
    if (tid < S) {
        float sum = 0.f;
#pragma unroll
        for (int k = 0; k < NOCT; k++) sum += g_rai[b][k][tid];
        rai = sum;
    }

    // ---- softmax over s ----
    float m = rai;
#pragma unroll
    for (int off = 16; off > 0; off >>= 1)
        m = fmaxf(m, __shfl_xor_sync(0xffffffff, m, off));
    if (lane == 0) red[wid] = m;
    __syncthreads();
    if (wid == 0) {
        float v = (lane < 8) ? red[lane] : -INFINITY;
#pragma unroll
        for (int off = 4; off > 0; off >>= 1)
            v = fmaxf(v, __shfl_xor_sync(0xffffffff, v, off));
        if (lane == 0) red[0] = v;
    }
    __syncthreads();
    const float gmax = red[0];
    __syncthreads();

    float p = (tid < S) ? expf(rai - gmax) : 0.f;
    float sacc = p;
#pragma unroll
    for (int off = 16; off > 0; off >>= 1)
        sacc += __shfl_xor_sync(0xffffffff, sacc, off);
    if (lane == 0) red[wid] = sacc;
    __syncthreads();
    if (wid == 0) {
        float v = (lane < 8) ? red[lane] : 0.f;
#pragma unroll
        for (int off = 4; off > 0; off >>= 1)
            v += __shfl_xor_sync(0xffffffff, v, off);
        if (lane == 0) red[0] = v;
    }
    __syncthreads();
    const float inv_sum = 1.f / red[0];
    if (tid < S) rvi_s[tid] = p * inv_sum;
    if (tid >= S && tid < 208) rvi_s[tid] = 0.f;
    __syncthreads();

    const float4 rA = *reinterpret_cast<const float4*>(&rvi_s[4 * lane]);
    const float4 rB = *reinterpret_cast<const float4*>(&rvi_s[128 + 4 * l2]);

    // ---- Pass 2: weighted sum from smem (8 rows per warp) ----
#pragma unroll
    for (int r = wid; r < OROWS; r += 8) {
        const float4* __restrict__ row = reinterpret_cast<const float4*>(&kb_s[r * S]);
        float4 va = row[lane];
        float4 vb = row[32 + l2];
        float sum = va.x * rA.x + va.y * rA.y + va.z * rA.z + va.w * rA.w
                  + mB * (vb.x * rB.x + vb.y * rB.y + vb.z * rB.z + vb.w * rB.w);
#pragma unroll
        for (int off = 16; off > 0; off >>= 1)
            sum += __shfl_xor_sync(0xffffffff, sum, off);
        if (lane == 0) out[b * D + oct * OROWS + r] = sum;
    }
}

extern "C" void kernel_launch(void* const* d_in, const int* in_sizes, int n_in,
                              void* d_out, int out_size)
{
    const float* memory = (const float*)d_in[0];  // [B, D]
    const float* ctrl   = (const float*)d_in[1];  // [B, D]
    const float* kb     = (const float*)d_in[2];  // [B, D, S]
    const float* W      = (const float*)d_in[3];  // [D, D]
    // d_in[4] = b_concat: s-independent shift inside softmax -> drops out
    const float* w_attn = (const float*)d_in[5];  // [D]
    float* out = (float*)d_out;                   // [B, D]

    const int tile_smem = TILE_B;                 // 50176 B
    cudaFuncSetAttribute(fused_kernel,
                         cudaFuncAttributeMaxDynamicSharedMemorySize, tile_smem);

    gemm_kernel<<<dim3(32, NKQ), 256>>>(ctrl, W, w_attn);
    fused_kernel<<<NOCT * BATCH, 256, tile_smem>>>(kb, memory, ctrl, w_attn, out);
}